// round 2
// baseline (speedup 1.0000x reference)
#include <cuda_runtime.h>
#include <math.h>

// Problem constants
#define T_STEPS 16384
#define HDIM    1024
#define XDIM    256

// Recurrent kernel config
#define NCTA          128   // persistent CTAs (<= 148 SMs -> expected co-resident)
#define ROWS_PER_CTA  8     // HDIM / NCTA
#define RNN_THREADS   256   // 8 warps, one row per warp
#define WATCHDOG_CYC  400000000LL   // ~0.2 s: poll watchdog before abort

// Scratch (device globals: allocation-free per harness rules)
__device__ float g_bx[(size_t)T_STEPS * HDIM];   // Bx_c precompute, 64 MB
__device__ __align__(16) int g_flags[NCTA];
__device__ int g_abort;

// ---------------------------------------------------------------------------
// helpers
// ---------------------------------------------------------------------------
__device__ __forceinline__ int4 ldcg_v4(const int4* p) {
    int4 v;
    asm volatile("ld.global.cg.v4.u32 {%0,%1,%2,%3}, [%4];"
                 : "=r"(v.x), "=r"(v.y), "=r"(v.z), "=r"(v.w)
                 : "l"(p)
                 : "memory");
    return v;
}

__device__ __forceinline__ int ldcg_i32(const int* p) {
    int v;
    asm volatile("ld.global.cg.s32 %0, [%1];" : "=r"(v) : "l"(p) : "memory");
    return v;
}

__device__ __forceinline__ float4 ldcg_f4(const float4* p) {
    float4 v;
    asm volatile("ld.global.cg.v4.f32 {%0,%1,%2,%3}, [%4];"
                 : "=f"(v.x), "=f"(v.y), "=f"(v.z), "=f"(v.w)
                 : "l"(p)
                 : "memory");
    return v;
}

__device__ __forceinline__ void st_release_gpu(int* p, int v) {
    asm volatile("st.release.gpu.global.s32 [%0], %1;" :: "l"(p), "r"(v) : "memory");
}

__device__ __forceinline__ void stg_i32(int* p, int v) {
    asm volatile("st.global.s32 [%0], %1;" :: "l"(p), "r"(v) : "memory");
}

__device__ __forceinline__ void fence_acq() {
    asm volatile("fence.acq_rel.gpu;" ::: "memory");
}

// ---------------------------------------------------------------------------
// 0) zero flags + abort (graph replays reuse device globals -> re-init)
// ---------------------------------------------------------------------------
__global__ void init_flags_kernel() {
    if (threadIdx.x < NCTA) g_flags[threadIdx.x] = 0;
    if (threadIdx.x == 0)  g_abort = 0;
}

// ---------------------------------------------------------------------------
// 1) Bx_c = x_seq @ B^T + c   (T x H), fp32 tiled GEMM
//    BM=128, BN=64, BK=32, 256 threads, 8x4 micro-tile
// ---------------------------------------------------------------------------
__global__ __launch_bounds__(256) void gemm_bx_kernel(
    const float* __restrict__ x,   // (T, 256)
    const float* __restrict__ B,   // (1024, 256)
    const float* __restrict__ c)   // (1024,)
{
    __shared__ float xsT[32][132];  // [k][t-row], padded
    __shared__ float bsT[32][68];   // [k][j-row], padded

    const int bj  = blockIdx.x * 64;
    const int bt  = blockIdx.y * 128;
    const int tid = threadIdx.x;
    const int tx  = tid & 15;   // 16 j-groups of 4 cols
    const int ty  = tid >> 4;   // 16 t-groups of 8 rows

    float acc[8][4];
#pragma unroll
    for (int i = 0; i < 8; i++)
#pragma unroll
        for (int j = 0; j < 4; j++) acc[i][j] = 0.0f;

    for (int k0 = 0; k0 < XDIM; k0 += 32) {
#pragma unroll
        for (int i = 0; i < 4; i++) {
            int idx = tid + i * 256;
            int r   = idx >> 3;
            int kk4 = (idx & 7) * 4;
            float4 v = *(const float4*)&x[(size_t)(bt + r) * XDIM + k0 + kk4];
            xsT[kk4 + 0][r] = v.x; xsT[kk4 + 1][r] = v.y;
            xsT[kk4 + 2][r] = v.z; xsT[kk4 + 3][r] = v.w;
        }
#pragma unroll
        for (int i = 0; i < 2; i++) {
            int idx = tid + i * 256;
            int r   = idx >> 3;
            int kk4 = (idx & 7) * 4;
            float4 v = *(const float4*)&B[(size_t)(bj + r) * XDIM + k0 + kk4];
            bsT[kk4 + 0][r] = v.x; bsT[kk4 + 1][r] = v.y;
            bsT[kk4 + 2][r] = v.z; bsT[kk4 + 3][r] = v.w;
        }
        __syncthreads();

#pragma unroll
        for (int kk = 0; kk < 32; kk++) {
            float xr[8], br[4];
#pragma unroll
            for (int i = 0; i < 8; i++) xr[i] = xsT[kk][ty * 8 + i];
#pragma unroll
            for (int j = 0; j < 4; j++) br[j] = bsT[kk][tx * 4 + j];
#pragma unroll
            for (int i = 0; i < 8; i++)
#pragma unroll
                for (int j = 0; j < 4; j++)
                    acc[i][j] = fmaf(xr[i], br[j], acc[i][j]);
        }
        __syncthreads();
    }

#pragma unroll
    for (int i = 0; i < 8; i++) {
        int t = bt + ty * 8 + i;
#pragma unroll
        for (int j = 0; j < 4; j++) {
            int col = bj + tx * 4 + j;
            g_bx[(size_t)t * HDIM + col] = acc[i][j] + c[col];
        }
    }
}

// ---------------------------------------------------------------------------
// 2) persistent recurrent kernel (fast path), with hang-proof watchdog.
//    CTA b owns rows [8b, 8b+8); warp w -> row 8b+w; lane l holds
//    A[row, 32l..32l+31] in registers (A = 0.9*I + 0.1*A_raw folded in).
// ---------------------------------------------------------------------------
__global__ __launch_bounds__(RNN_THREADS, 1) void rnn_scan_kernel(
    const float* __restrict__ A_raw,  // (1024, 1024)
    const float* __restrict__ h0,     // (1024,)
    float* __restrict__ out)          // (16384, 1024)
{
    __shared__ int s_abort;
    const int b   = blockIdx.x;
    const int w   = threadIdx.x >> 5;
    const int l   = threadIdx.x & 31;
    const int row = b * ROWS_PER_CTA + w;

    if (threadIdx.x == 0) s_abort = 0;

    // Load A row segment into registers, applying A = 0.9*I + 0.1*A_raw
    float4 a[8];
#pragma unroll
    for (int i = 0; i < 8; i++) {
        int col  = 32 * l + 4 * i;
        float4 v = *(const float4*)&A_raw[(size_t)row * HDIM + col];
        v.x *= 0.1f; v.y *= 0.1f; v.z *= 0.1f; v.w *= 0.1f;
        int d = row - col;
        if (d == 0) v.x += 0.9f;
        else if (d == 1) v.y += 0.9f;
        else if (d == 2) v.z += 0.9f;
        else if (d == 3) v.w += 0.9f;
        a[i] = v;
    }
    __syncthreads();

    const float* hprev = h0;

    for (int t = 0; t < T_STEPS; t++) {
        // bias prefetch (independent of h -> overlaps poll)
        float bxv = 0.0f;
        if (l == 0) bxv = g_bx[(size_t)t * HDIM + row];

        if (t > 0) {
            if (w == 0) {
                bool aborted = false;
                long long t0 = clock64();
                const int4* f4 = (const int4*)g_flags;  // lane l: flags[4l..4l+3]
                for (;;) {
                    int4 f  = ldcg_v4(&f4[l]);
                    bool ok = (f.x >= t) & (f.y >= t) & (f.z >= t) & (f.w >= t);
                    if (__all_sync(0xffffffffu, ok)) break;
                    int ab = 0;
                    if (l == 0) {
                        ab = ldcg_i32(&g_abort);
                        if (!ab && (clock64() - t0) > WATCHDOG_CYC) {
                            stg_i32(&g_abort, 1);
                            ab = 1;
                        }
                    }
                    if (__shfl_sync(0xffffffffu, ab, 0)) { aborted = true; break; }
                }
                if (!aborted) fence_acq();
                if (threadIdx.x == 0 && aborted) s_abort = 1;
            }
            __syncthreads();
            if (s_abort) return;   // uniform: fallback kernel will recompute
            hprev = out + (size_t)(t - 1) * HDIM;
        }

        // dot product: 32 contiguous elements per lane, L2-coherent loads
        const float4* h4 = (const float4*)(hprev + 32 * l);
        float a0 = 0.f, a1 = 0.f, a2 = 0.f, a3 = 0.f;
#pragma unroll
        for (int i = 0; i < 8; i++) {
            float4 hv = ldcg_f4(&h4[i]);
            a0 = fmaf(a[i].x, hv.x, a0);
            a1 = fmaf(a[i].y, hv.y, a1);
            a2 = fmaf(a[i].z, hv.z, a2);
            a3 = fmaf(a[i].w, hv.w, a3);
        }
        float acc = (a0 + a1) + (a2 + a3);
#pragma unroll
        for (int s = 16; s > 0; s >>= 1)
            acc += __shfl_xor_sync(0xffffffffu, acc, s);

        if (l == 0) {
            out[(size_t)t * HDIM + row] = tanhf(acc + bxv);
        }

        __syncthreads();  // all 8 rows stored before publishing
        if (threadIdx.x == 0) st_release_gpu(&g_flags[b], t + 1);
    }
}

// ---------------------------------------------------------------------------
// 3) fallback: single-CTA full recompute; runs only if g_abort was set.
//    warp per row-group; h kept in smem; A streamed from L2.
//    out_row = tanh(0.1*dot(A_raw_row, h) + 0.9*h[row] + bx)
// ---------------------------------------------------------------------------
__global__ __launch_bounds__(1024) void fallback_scan_kernel(
    const float* __restrict__ A_raw,
    const float* __restrict__ h0,
    float* __restrict__ out)
{
    if (g_abort == 0) return;

    __shared__ float h[HDIM];
    __shared__ float hn[HDIM];
    const int tid = threadIdx.x;
    const int w   = tid >> 5;
    const int l   = tid & 31;

    h[tid] = h0[tid];
    __syncthreads();

    for (int t = 0; t < T_STEPS; t++) {
        for (int r = w; r < HDIM; r += 32) {
            const float* Ar = A_raw + (size_t)r * HDIM;
            float acc = 0.0f;
#pragma unroll 8
            for (int k = l; k < HDIM; k += 32)
                acc = fmaf(Ar[k], h[k], acc);
#pragma unroll
            for (int s = 16; s > 0; s >>= 1)
                acc += __shfl_xor_sync(0xffffffffu, acc, s);
            if (l == 0) {
                float v = tanhf(0.1f * acc + 0.9f * h[r] +
                                g_bx[(size_t)t * HDIM + r]);
                hn[r] = v;
                out[(size_t)t * HDIM + r] = v;
            }
        }
        __syncthreads();
        h[tid] = hn[tid];
        __syncthreads();
    }
}

// ---------------------------------------------------------------------------
// launch
// ---------------------------------------------------------------------------
extern "C" void kernel_launch(void* const* d_in, const int* in_sizes, int n_in,
                              void* d_out, int out_size) {
    const float* x_seq = (const float*)d_in[0];  // (16384, 256)
    const float* h0    = (const float*)d_in[1];  // (1024,)
    const float* A_raw = (const float*)d_in[2];  // (1024, 1024)
    const float* B     = (const float*)d_in[3];  // (1024, 256)
    const float* c     = (const float*)d_in[4];  // (1024,)
    float* out = (float*)d_out;                  // (16384, 1024)

    init_flags_kernel<<<1, 128>>>();
    gemm_bx_kernel<<<dim3(HDIM / 64, T_STEPS / 128), 256>>>(x_seq, B, c);
    rnn_scan_kernel<<<NCTA, RNN_THREADS>>>(A_raw, h0, out);
    fallback_scan_kernel<<<1, 1024>>>(A_raw, h0, out);
}

// round 3
// speedup vs baseline: 4.1094x; 4.1094x over previous
#include <cuda_runtime.h>
#include <math.h>

// Problem constants
#define T_STEPS 16384
#define HDIM    1024
#define XDIM    256

// Recurrent kernel config
#define NCTA          128   // persistent CTAs (<= 148 SMs -> co-resident in wave 1)
#define ROWS_PER_CTA  8     // HDIM / NCTA
#define RNN_THREADS   256   // 8 warps, one row per warp
#define WATCHDOG_CYC  400000000LL   // ~0.2 s poll watchdog before abort

// Scratch (device globals: allocation-free per harness rules)
__device__ float g_bx[(size_t)T_STEPS * HDIM];   // Bx_c precompute, 64 MB
__device__ int   g_cnt[T_STEPS];                 // per-step arrival counter
__device__ int   g_abort;

// ---------------------------------------------------------------------------
// helpers
// ---------------------------------------------------------------------------
__device__ __forceinline__ int ld_acquire_gpu(const int* p) {
    int v;
    asm volatile("ld.acquire.gpu.global.s32 %0, [%1];" : "=r"(v) : "l"(p) : "memory");
    return v;
}

__device__ __forceinline__ void red_release_add(int* p, int v) {
    asm volatile("red.release.gpu.global.add.s32 [%0], %1;" :: "l"(p), "r"(v) : "memory");
}

__device__ __forceinline__ int ldcg_i32(const int* p) {
    int v;
    asm volatile("ld.global.cg.s32 %0, [%1];" : "=r"(v) : "l"(p) : "memory");
    return v;
}

__device__ __forceinline__ void stg_i32(int* p, int v) {
    asm volatile("st.global.s32 [%0], %1;" :: "l"(p), "r"(v) : "memory");
}

// ---------------------------------------------------------------------------
// 0) zero counters + abort (graph replays reuse device globals -> re-init)
//    grid 16 x 1024 = 16384 threads
// ---------------------------------------------------------------------------
__global__ void init_cnt_kernel() {
    int i = blockIdx.x * blockDim.x + threadIdx.x;
    g_cnt[i] = 0;
    if (i == 0) g_abort = 0;
}

// ---------------------------------------------------------------------------
// 1) Bx_c = x_seq @ B^T + c   (T x H), fp32 tiled GEMM
//    BM=128, BN=64, BK=32, 256 threads, 8x4 micro-tile
// ---------------------------------------------------------------------------
__global__ __launch_bounds__(256) void gemm_bx_kernel(
    const float* __restrict__ x,   // (T, 256)
    const float* __restrict__ B,   // (1024, 256)
    const float* __restrict__ c)   // (1024,)
{
    __shared__ float xsT[32][132];  // [k][t-row], padded
    __shared__ float bsT[32][68];   // [k][j-row], padded

    const int bj  = blockIdx.x * 64;
    const int bt  = blockIdx.y * 128;
    const int tid = threadIdx.x;
    const int tx  = tid & 15;
    const int ty  = tid >> 4;

    float acc[8][4];
#pragma unroll
    for (int i = 0; i < 8; i++)
#pragma unroll
        for (int j = 0; j < 4; j++) acc[i][j] = 0.0f;

    for (int k0 = 0; k0 < XDIM; k0 += 32) {
#pragma unroll
        for (int i = 0; i < 4; i++) {
            int idx = tid + i * 256;
            int r   = idx >> 3;
            int kk4 = (idx & 7) * 4;
            float4 v = *(const float4*)&x[(size_t)(bt + r) * XDIM + k0 + kk4];
            xsT[kk4 + 0][r] = v.x; xsT[kk4 + 1][r] = v.y;
            xsT[kk4 + 2][r] = v.z; xsT[kk4 + 3][r] = v.w;
        }
#pragma unroll
        for (int i = 0; i < 2; i++) {
            int idx = tid + i * 256;
            int r   = idx >> 3;
            int kk4 = (idx & 7) * 4;
            float4 v = *(const float4*)&B[(size_t)(bj + r) * XDIM + k0 + kk4];
            bsT[kk4 + 0][r] = v.x; bsT[kk4 + 1][r] = v.y;
            bsT[kk4 + 2][r] = v.z; bsT[kk4 + 3][r] = v.w;
        }
        __syncthreads();

#pragma unroll
        for (int kk = 0; kk < 32; kk++) {
            float xr[8], br[4];
#pragma unroll
            for (int i = 0; i < 8; i++) xr[i] = xsT[kk][ty * 8 + i];
#pragma unroll
            for (int j = 0; j < 4; j++) br[j] = bsT[kk][tx * 4 + j];
#pragma unroll
            for (int i = 0; i < 8; i++)
#pragma unroll
                for (int j = 0; j < 4; j++)
                    acc[i][j] = fmaf(xr[i], br[j], acc[i][j]);
        }
        __syncthreads();
    }

#pragma unroll
    for (int i = 0; i < 8; i++) {
        int t = bt + ty * 8 + i;
#pragma unroll
        for (int j = 0; j < 4; j++) {
            int col = bj + tx * 4 + j;
            g_bx[(size_t)t * HDIM + col] = acc[i][j] + c[col];
        }
    }
}

// ---------------------------------------------------------------------------
// 2) persistent recurrent kernel (fast path), counter sync, hang-proof.
//    CTA b owns rows [8b, 8b+8); warp w -> row 8b+w; lane l holds
//    A[row, 32l..32l+31] in registers (A = 0.9*I + 0.1*A_raw folded in).
//    Sync per step: CTA -> bar -> thread0 red.release.gpu.add(cnt[t], 1);
//    consumer thread0 polls ld.acquire.gpu(cnt[t-1]) == NCTA -> bar.
// ---------------------------------------------------------------------------
__global__ __launch_bounds__(RNN_THREADS, 1) void rnn_scan_kernel(
    const float* __restrict__ A_raw,  // (1024, 1024)
    const float* __restrict__ h0,     // (1024,)
    float* __restrict__ out)          // (16384, 1024)
{
    __shared__ int s_abort;
    const int b   = blockIdx.x;
    const int w   = threadIdx.x >> 5;
    const int l   = threadIdx.x & 31;
    const int row = b * ROWS_PER_CTA + w;

    if (threadIdx.x == 0) s_abort = 0;

    // Load A row segment into registers, applying A = 0.9*I + 0.1*A_raw
    float4 a[8];
#pragma unroll
    for (int i = 0; i < 8; i++) {
        int col  = 32 * l + 4 * i;
        float4 v = *(const float4*)&A_raw[(size_t)row * HDIM + col];
        v.x *= 0.1f; v.y *= 0.1f; v.z *= 0.1f; v.w *= 0.1f;
        int d = row - col;
        if (d == 0) v.x += 0.9f;
        else if (d == 1) v.y += 0.9f;
        else if (d == 2) v.z += 0.9f;
        else if (d == 3) v.w += 0.9f;
        a[i] = v;
    }
    __syncthreads();

    const float* hprev = h0;

    for (int t = 0; t < T_STEPS; t++) {
        // bias prefetch (independent of h -> overlaps poll)
        float bxv = 0.0f;
        if (l == 0) bxv = g_bx[(size_t)t * HDIM + row];

        if (t > 0) {
            if (threadIdx.x == 0) {
                long long t0 = clock64();
                const int* cp = &g_cnt[t - 1];
                for (;;) {
                    if (ld_acquire_gpu(cp) >= NCTA) break;
                    if (ldcg_i32(&g_abort)) { s_abort = 1; break; }
                    if ((clock64() - t0) > WATCHDOG_CYC) {
                        stg_i32(&g_abort, 1);
                        s_abort = 1;
                        break;
                    }
                }
            }
            __syncthreads();
            if (s_abort) return;   // uniform exit: fallback recomputes
            hprev = out + (size_t)(t - 1) * HDIM;
        }

        // dot product: 32 contiguous elements per lane (fresh lines, plain LDG)
        const float4* h4 = (const float4*)(hprev + 32 * l);
        float a0 = 0.f, a1 = 0.f, a2 = 0.f, a3 = 0.f;
#pragma unroll
        for (int i = 0; i < 8; i++) {
            float4 hv = h4[i];
            a0 = fmaf(a[i].x, hv.x, a0);
            a1 = fmaf(a[i].y, hv.y, a1);
            a2 = fmaf(a[i].z, hv.z, a2);
            a3 = fmaf(a[i].w, hv.w, a3);
        }
        float acc = (a0 + a1) + (a2 + a3);
#pragma unroll
        for (int s = 16; s > 0; s >>= 1)
            acc += __shfl_xor_sync(0xffffffffu, acc, s);

        if (l == 0) {
            out[(size_t)t * HDIM + row] = tanhf(acc + bxv);
        }

        __syncthreads();  // all 8 rows stored before publishing
        if (threadIdx.x == 0) red_release_add(&g_cnt[t], 1);
    }
}

// ---------------------------------------------------------------------------
// 3) fallback: single-CTA full recompute; runs only if g_abort was set.
// ---------------------------------------------------------------------------
__global__ __launch_bounds__(1024) void fallback_scan_kernel(
    const float* __restrict__ A_raw,
    const float* __restrict__ h0,
    float* __restrict__ out)
{
    if (g_abort == 0) return;

    __shared__ float h[HDIM];
    __shared__ float hn[HDIM];
    const int tid = threadIdx.x;
    const int w   = tid >> 5;
    const int l   = tid & 31;

    h[tid] = h0[tid];
    __syncthreads();

    for (int t = 0; t < T_STEPS; t++) {
        for (int r = w; r < HDIM; r += 32) {
            const float* Ar = A_raw + (size_t)r * HDIM;
            float acc = 0.0f;
#pragma unroll 8
            for (int k = l; k < HDIM; k += 32)
                acc = fmaf(Ar[k], h[k], acc);
#pragma unroll
            for (int s = 16; s > 0; s >>= 1)
                acc += __shfl_xor_sync(0xffffffffu, acc, s);
            if (l == 0) {
                float v = tanhf(0.1f * acc + 0.9f * h[r] +
                                g_bx[(size_t)t * HDIM + r]);
                hn[r] = v;
                out[(size_t)t * HDIM + r] = v;
            }
        }
        __syncthreads();
        h[tid] = hn[tid];
        __syncthreads();
    }
}

// ---------------------------------------------------------------------------
// launch
// ---------------------------------------------------------------------------
extern "C" void kernel_launch(void* const* d_in, const int* in_sizes, int n_in,
                              void* d_out, int out_size) {
    const float* x_seq = (const float*)d_in[0];  // (16384, 256)
    const float* h0    = (const float*)d_in[1];  // (1024,)
    const float* A_raw = (const float*)d_in[2];  // (1024, 1024)
    const float* B     = (const float*)d_in[3];  // (1024, 256)
    const float* c     = (const float*)d_in[4];  // (1024,)
    float* out = (float*)d_out;                  // (16384, 1024)

    init_cnt_kernel<<<16, 1024>>>();
    gemm_bx_kernel<<<dim3(HDIM / 64, T_STEPS / 128), 256>>>(x_seq, B, c);
    rnn_scan_kernel<<<NCTA, RNN_THREADS>>>(A_raw, h0, out);
    fallback_scan_kernel<<<1, 1024>>>(A_raw, h0, out);
}